// round 7
// baseline (speedup 1.0000x reference)
#include <cuda_runtime.h>

// SPDUnVectorize: x[B, L] packed upper triangle (row-major, incl. diag) ->
// out[B, n, n] symmetric. B=1024, n=256, L=n(n+1)/2=32896.
//
// Warp-private tiles: each warp handles one 32x32 tile for its own batch
// (8 batches per block). No __syncthreads -- only __syncwarp. Upper tile
// stored straight from registers; mirror via XOR-swizzled 4KB smem tile.

#define NMAT   256
#define L_IN   32896
#define BATCH  1024
#define TILE   32
#define NTROW  8
#define NTILES 36
#define NWARP  8

__device__ __forceinline__ int tri_off(int r) {
    return r * NMAT - (r * (r - 1)) / 2;
}

__global__ __launch_bounds__(256, 7)
void spd_unvec_kernel(const float* __restrict__ in, float* __restrict__ out) {
    __shared__ float s[NWARP][TILE * TILE];   // 32KB, XOR-swizzled per warp

    int t = blockIdx.x;
    int ti = 0;
    int rem = NTROW;
    while (t >= rem) { t -= rem; rem--; ti++; }
    const int tj = ti + t;

    const int w    = threadIdx.x >> 5;
    const int lane = threadIdx.x & 31;
    const int b    = blockIdx.y * NWARP + w;

    const float* __restrict__ inb  = in  + (size_t)b * L_IN;
    float*       __restrict__ outb = out + (size_t)b * (NMAT * NMAT);
    float* __restrict__ sw = s[w];

    if (ti == tj) {
        const int R = ti * TILE;
        // Load upper half of diagonal tile (cols >= row), swizzled smem.
        #pragma unroll
        for (int chunk = 0; chunk < 4; chunk++) {
            float v[8];
            #pragma unroll
            for (int k = 0; k < 8; k++) {
                const int lr = chunk * 8 + k;
                if (lane >= lr) v[k] = inb[tri_off(R + lr) + lane - lr];
            }
            #pragma unroll
            for (int k = 0; k < 8; k++) {
                const int lr = chunk * 8 + k;
                if (lane >= lr) sw[lr * 32 + (lane ^ lr)] = v[k];
            }
        }
        __syncwarp();
        // Emit full tile: select upper/transposed; bank = lane^mr both ways.
        #pragma unroll
        for (int mr = 0; mr < 32; mr++) {
            const int idx = (lane >= mr) ? (mr * 32 + (lane ^ mr))
                                         : (lane * 32 + (mr ^ lane));
            outb[(R + mr) * NMAT + R + lane] = sw[idx];
        }
    } else {
        // Off-diagonal tile (ti < tj).
        #pragma unroll
        for (int chunk = 0; chunk < 4; chunk++) {
            float v[8];
            #pragma unroll
            for (int k = 0; k < 8; k++) {
                const int lr = chunk * 8 + k;
                const int r  = ti * TILE + lr;
                v[k] = inb[tri_off(r) - r + tj * TILE + lane];
            }
            #pragma unroll
            for (int k = 0; k < 8; k++) {
                const int lr = chunk * 8 + k;
                const int r  = ti * TILE + lr;
                outb[r * NMAT + tj * TILE + lane] = v[k];   // upper, direct
                sw[lr * 32 + (lane ^ lr)] = v[k];           // stage for mirror
            }
        }
        __syncwarp();
        // Mirror tile: transposed read, conflict-free (bank = mr^lane).
        #pragma unroll
        for (int mr = 0; mr < 32; mr++) {
            outb[(tj * TILE + mr) * NMAT + ti * TILE + lane] =
                sw[lane * 32 + (mr ^ lane)];
        }
    }
}

extern "C" void kernel_launch(void* const* d_in, const int* in_sizes, int n_in,
                              void* d_out, int out_size) {
    const float* in = (const float*)d_in[0];
    float* out = (float*)d_out;
    dim3 grid(NTILES, BATCH / NWARP);
    dim3 block(256);
    spd_unvec_kernel<<<grid, block>>>(in, out);
}

// round 8
// speedup vs baseline: 1.8761x; 1.8761x over previous
#include <cuda_runtime.h>

// SPDUnVectorize: x[B, L] packed upper triangle (row-major, incl. diag) ->
// out[B, n, n] symmetric. B=1024, n=256, L=n(n+1)/2=32896.
//
// R5 skeleton (one block = one 32x32 tile x 2 batches) with two edits:
//  - upper tile stored DIRECTLY from load registers before the barrier
//  - all 8 loads register-staged first (front-batched MLP)

#define NMAT   256
#define L_IN   32896
#define BATCH  1024
#define TILE   32
#define NTROW  8
#define NTILES 36
#define PAD    33

__device__ __forceinline__ int tri_off(int r) {
    return r * NMAT - (r * (r - 1)) / 2;
}

__global__ __launch_bounds__(256, 7)
void spd_unvec_kernel(const float* __restrict__ in, float* __restrict__ out) {
    __shared__ float s0[TILE][PAD];
    __shared__ float s1[TILE][PAD];

    const int b0 = blockIdx.y * 2;
    int t = blockIdx.x;

    int ti = 0;
    int rem = NTROW;
    while (t >= rem) { t -= rem; rem--; ti++; }
    const int tj = ti + t;

    const int lane = threadIdx.x & 31;   // column within tile
    const int wy   = threadIdx.x >> 5;   // 0..7 (base row)

    const float* __restrict__ in0  = in  + (size_t)b0 * L_IN;
    const float* __restrict__ in1  = in0 + L_IN;
    float*       __restrict__ out0 = out + (size_t)b0 * (NMAT * NMAT);
    float*       __restrict__ out1 = out0 + (NMAT * NMAT);

    if (ti == tj) {
        // ---- Diagonal tile, both batches (through smem; 8/36 tiles) ----
        #pragma unroll
        for (int k = 0; k < 4; k++) {
            const int lr = wy + k * 8;
            const int r  = ti * TILE + lr;
            if (lane >= lr) {
                const int idx = tri_off(r) + lane - lr;
                s0[lr][lane] = in0[idx];
                s1[lr][lane] = in1[idx];
            }
        }
        __syncthreads();
        const int row = threadIdx.x >> 3;
        const int qc  = (threadIdx.x & 7) << 2;
        const int r   = ti * TILE + row;
        float4 v0, v1;
        #pragma unroll
        for (int k = 0; k < 4; k++) {
            const int c  = qc + k;
            const bool up = (c >= row);
            ((float*)&v0)[k] = up ? s0[row][c] : s0[c][row];
            ((float*)&v1)[k] = up ? s1[row][c] : s1[c][row];
        }
        *reinterpret_cast<float4*>(&out0[r * NMAT + ti * TILE + qc]) = v0;
        *reinterpret_cast<float4*>(&out1[r * NMAT + ti * TILE + qc]) = v1;
    } else {
        // ---- Off-diagonal tile (ti < tj), both batches ----
        // Stage all 8 loads (4 rows x 2 batches) in registers first.
        float v0[4], v1[4];
        #pragma unroll
        for (int k = 0; k < 4; k++) {
            const int lr  = wy + k * 8;
            const int r   = ti * TILE + lr;
            const int idx = tri_off(r) - r + tj * TILE + lane;
            v0[k] = in0[idx];
            v1[k] = in1[idx];
        }
        // Upper tile: store DIRECTLY from registers (coalesced 128B rows),
        // overlapping with nothing blocking -- before the barrier.
        #pragma unroll
        for (int k = 0; k < 4; k++) {
            const int lr = wy + k * 8;
            const int r  = ti * TILE + lr;
            out0[r * NMAT + tj * TILE + lane] = v0[k];
            out1[r * NMAT + tj * TILE + lane] = v1[k];
            s0[lr][lane] = v0[k];
            s1[lr][lane] = v1[k];
        }
        __syncthreads();

        // Mirror tile only: transposed smem read -> one STG.128 per batch.
        const int row = threadIdx.x >> 3;
        const int qc  = (threadIdx.x & 7) << 2;
        const int r2  = tj * TILE + row;

        float4 m0, m1;
        #pragma unroll
        for (int k = 0; k < 4; k++) {
            const int c = qc + k;
            ((float*)&m0)[k] = s0[c][row];
            ((float*)&m1)[k] = s1[c][row];
        }
        *reinterpret_cast<float4*>(&out0[r2 * NMAT + ti * TILE + qc]) = m0;
        *reinterpret_cast<float4*>(&out1[r2 * NMAT + ti * TILE + qc]) = m1;
    }
}

extern "C" void kernel_launch(void* const* d_in, const int* in_sizes, int n_in,
                              void* d_out, int out_size) {
    const float* in = (const float*)d_in[0];
    float* out = (float*)d_out;
    dim3 grid(NTILES, BATCH / 2);
    dim3 block(256);
    spd_unvec_kernel<<<grid, block>>>(in, out);
}